// round 6
// baseline (speedup 1.0000x reference)
#include <cuda_runtime.h>
#include <cstdint>

#define PB   8192
#define PDIM 4096
#define PHID 256
#define PH   16
#define PSEQ 2048

// -------- device-global scratch (no allocs allowed) --------
__device__ float g_hidden[(size_t)PB * PDIM];      // 128 MB (tf32-rounded GEMM1 out)
__device__ float g_X[(size_t)PB * PDIM];           // 128 MB (tf32-rounded x)
__device__ float g_Wpt[(size_t)PH * PHID * PDIM];  // 64 MB  [n_global][k], tf32-rounded
__device__ float g_Wot[(size_t)PDIM * PDIM];       // 64 MB  [n][k], tf32-rounded
__device__ float g_coef[48];                       // w[16], cc[16], b[16]

// -------- helpers --------
__device__ __forceinline__ uint32_t smem_u32(const void* p) {
    uint32_t a;
    asm("{ .reg .u64 t; cvta.to.shared.u64 t, %1; cvt.u32.u64 %0, t; }" : "=r"(a) : "l"(p));
    return a;
}
__device__ __forceinline__ void cp16(uint32_t dst, const float* src) {
    asm volatile("cp.async.cg.shared.global [%0], [%1], 16;" :: "r"(dst), "l"(src));
}
__device__ __forceinline__ float rna_tf32(float v) {
    uint32_t u;
    asm("cvt.rna.tf32.f32 %0, %1;" : "=r"(u) : "f"(v));
    return __uint_as_float(u);
}
__device__ __forceinline__ void ldsm4(uint32_t* r, uint32_t addr) {
    asm volatile("ldmatrix.sync.aligned.m8n8.x4.shared.b16 {%0,%1,%2,%3}, [%4];"
                 : "=r"(r[0]), "=r"(r[1]), "=r"(r[2]), "=r"(r[3]) : "r"(addr));
}
__device__ __forceinline__ void mma_tf32(float* d, const uint32_t* a, const uint32_t* b) {
    asm volatile("mma.sync.aligned.m16n8k8.row.col.f32.tf32.tf32.f32 "
                 "{%0,%1,%2,%3}, {%4,%5,%6,%7}, {%8,%9}, {%0,%1,%2,%3};"
                 : "+f"(d[0]), "+f"(d[1]), "+f"(d[2]), "+f"(d[3])
                 : "r"(a[0]), "r"(a[1]), "r"(a[2]), "r"(a[3]), "r"(b[0]), "r"(b[1]));
}

// -------- small prep kernels --------
__global__ void coef_kernel(const float* __restrict__ w_mix,
                            const float* __restrict__ b_mix,
                            const float* __restrict__ decay_values,
                            const int* __restrict__ index_p) {
    int h = threadIdx.x;
    if (h < PH) {
        int idx = *index_p;
        float w = w_mix[h * PSEQ + idx];
        float b = b_mix[h * PSEQ + idx];
        float d = decay_values[h];
        d = fminf(fmaxf(d, 0.9f), 1.0f);
        d = powf(d, 0.25f);
        g_coef[h]      = w;
        g_coef[16 + h] = (h < PH / 2) ? (w * d) : d;
        g_coef[32 + h] = b;
    }
}

// tf32-rna elementwise convert (float4)
__global__ void cvt_kernel(const float* __restrict__ in, float* __restrict__ out, int n4) {
    int i = blockIdx.x * blockDim.x + threadIdx.x;
    if (i < n4) {
        float4 v = ((const float4*)in)[i];
        v.x = rna_tf32(v.x); v.y = rna_tf32(v.y);
        v.z = rna_tf32(v.z); v.w = rna_tf32(v.w);
        ((float4*)out)[i] = v;
    }
}

// out[b][c][r] = rna(in[b][r][c])
__global__ void transpose_kernel(const float* __restrict__ in, float* __restrict__ out,
                                 int rows, int cols) {
    __shared__ float t[32][33];
    const size_t bo = (size_t)blockIdx.z * rows * cols;
    const float* In = in + bo;
    float* Out = out + bo;
    int r0 = blockIdx.y * 32, c0 = blockIdx.x * 32;
#pragma unroll
    for (int i = threadIdx.y; i < 32; i += 8)
        t[i][threadIdx.x] = In[(size_t)(r0 + i) * cols + c0 + threadIdx.x];
    __syncthreads();
#pragma unroll
    for (int i = threadIdx.y; i < 32; i += 8)
        Out[(size_t)(c0 + i) * rows + r0 + threadIdx.x] = rna_tf32(t[threadIdx.x][i]);
}

// -------- TF32 mma.sync GEMM: C[8192,4096] = A[8192,4096] @ Bt[4096,4096]^T --------
// Bt is [N][K] k-contiguous. Tile 128x256x32, 8 warps (2Mx4N), 64x64 warp tile,
// 4-stage cp.async (issued at iter top so loads overlap MMAs),
// compiler-scheduled fragment loads (R4 structure — manual double-buffering regressed).
// MODE 1: head epilogue (+ rna to hidden); MODE 2: + bias.
template <int MODE>
__global__ void __launch_bounds__(256, 1)
gemm_mma(const float* __restrict__ A, const float* __restrict__ Bt,
         const float* __restrict__ bias, const float* __restrict__ caches,
         float* __restrict__ C) {
    constexpr int S = 4;
    constexpr int NCH = PDIM / 32;        // 128
    constexpr uint32_t A_BYTES = 128 * 128;   // 16 KB
    constexpr uint32_t STG = A_BYTES + 256 * 128;  // 48 KB

    extern __shared__ char smem[];
    const uint32_t sb = smem_u32(smem);
    const int tid = threadIdx.x;
    const int wid = tid >> 5, lane = tid & 31;
    const int wm = wid & 1;      // 2 warps along M
    const int wn = wid >> 1;     // 4 warps along N

    const int m0 = blockIdx.y * 128;
    const int n0 = blockIdx.x * 256;
    const float* Ab = A + (size_t)m0 * PDIM;
    const float* Bb = Bt + (size_t)n0 * PDIM;

    // per-thread cp.async coordinates (A: 4 chunks of 16B, B: 8 chunks)
    int ar[4], ac[4]; uint32_t asw[4];
    int br[8], bc[8]; uint32_t bsw[8];
#pragma unroll
    for (int j = 0; j < 4; j++) {
        int id = tid + j * 256;
        ar[j] = id >> 3; ac[j] = id & 7;
        asw[j] = (uint32_t)ar[j] * 128 + ((((uint32_t)ac[j]) * 16) ^ ((((uint32_t)ar[j]) & 7) << 4));
    }
#pragma unroll
    for (int j = 0; j < 8; j++) {
        int id = tid + j * 256;
        br[j] = id >> 3; bc[j] = id & 7;
        bsw[j] = (uint32_t)br[j] * 128 + ((((uint32_t)bc[j]) * 16) ^ ((((uint32_t)br[j]) & 7) << 4));
    }

    float acc[4][8][4];
#pragma unroll
    for (int mt = 0; mt < 4; mt++)
#pragma unroll
        for (int nt = 0; nt < 8; nt++)
#pragma unroll
            for (int e = 0; e < 4; e++) acc[mt][nt][e] = 0.0f;

    // ldmatrix per-thread base coords
    const int a_row = wm * 64 + (lane & 15);         // + mt*16
    const int a_grp = (lane >> 4);                   // + 2*ks
    const int b_row = wn * 64 + (lane & 7) + ((lane >> 4) << 3);   // + ntp*16
    const int b_grp = (lane >> 3) & 1;               // + 2*ks

    auto issue = [&](int c) {
        const float* ag = Ab + c * 32;
        const float* bg = Bb + c * 32;
        uint32_t st = sb + (uint32_t)(c & (S - 1)) * STG;
#pragma unroll
        for (int j = 0; j < 4; j++)
            cp16(st + asw[j], ag + (size_t)ar[j] * PDIM + ac[j] * 4);
#pragma unroll
        for (int j = 0; j < 8; j++)
            cp16(st + A_BYTES + bsw[j], bg + (size_t)br[j] * PDIM + bc[j] * 4);
    };

    // prologue: 3 stages
#pragma unroll
    for (int c = 0; c < S - 1; c++) {
        issue(c);
        asm volatile("cp.async.commit_group;" ::: "memory");
    }

    for (int i = 0; i < NCH; i++) {
        asm volatile("cp.async.wait_group %0;" :: "n"(S - 2) : "memory");
        __syncthreads();

        // issue next stage FIRST so its cp.asyncs overlap this iter's MMAs
        int c = i + S - 1;
        if (c < NCH) issue(c);
        asm volatile("cp.async.commit_group;" ::: "memory");

        uint32_t sa = sb + (uint32_t)(i & (S - 1)) * STG;
        uint32_t sB = sa + A_BYTES;

#pragma unroll
        for (int ks = 0; ks < 4; ks++) {
            uint32_t af[4][4], bf[4][4];
#pragma unroll
            for (int mt = 0; mt < 4; mt++) {
                int rr = a_row + mt * 16;
                int gg = 2 * ks + a_grp;
                ldsm4(af[mt], sa + (uint32_t)rr * 128 +
                              ((((uint32_t)gg) << 4) ^ ((((uint32_t)rr) & 7) << 4)));
            }
#pragma unroll
            for (int ntp = 0; ntp < 4; ntp++) {
                int rr = b_row + ntp * 16;
                int gg = 2 * ks + b_grp;
                ldsm4(bf[ntp], sB + (uint32_t)rr * 128 +
                               ((((uint32_t)gg) << 4) ^ ((((uint32_t)rr) & 7) << 4)));
            }
#pragma unroll
            for (int mt = 0; mt < 4; mt++)
#pragma unroll
                for (int nt = 0; nt < 8; nt++)
                    mma_tf32(acc[mt][nt], af[mt], &bf[nt >> 1][(nt & 1) * 2]);
        }
    }

    // -------- epilogue --------
    const int r = lane >> 2, qc = lane & 3;
    float wv = 0.f, ccf = 0.f, bvv = 0.f;
    if (MODE == 1) {
        wv  = g_coef[blockIdx.x];
        ccf = g_coef[16 + blockIdx.x];
        bvv = g_coef[32 + blockIdx.x];
    }
#pragma unroll
    for (int mt = 0; mt < 4; mt++) {
        const int grow0 = m0 + wm * 64 + mt * 16 + r;
#pragma unroll
        for (int nt = 0; nt < 8; nt++) {
            const int cloc = wn * 64 + nt * 8 + 2 * qc;   // col within 256-wide tile
            const int gcol = n0 + cloc;
            if (MODE == 1) {
                const float2 bp = *(const float2*)&bias[blockIdx.x * PHID + cloc];
#pragma unroll
                for (int h2 = 0; h2 < 2; h2++) {
                    const int grow = grow0 + h2 * 8;
                    const float2 cv = *(const float2*)
                        &caches[((size_t)blockIdx.x * PB + grow) * PHID + cloc];
                    float2 o;
                    o.x = rna_tf32(wv * (acc[mt][nt][h2 * 2 + 0] + bp.x) + ccf * cv.x + bvv);
                    o.y = rna_tf32(wv * (acc[mt][nt][h2 * 2 + 1] + bp.y) + ccf * cv.y + bvv);
                    *(float2*)&C[(size_t)grow * PDIM + gcol] = o;
                }
            } else {
                const float2 bp = *(const float2*)&bias[gcol];
#pragma unroll
                for (int h2 = 0; h2 < 2; h2++) {
                    const int grow = grow0 + h2 * 8;
                    float2 o;
                    o.x = acc[mt][nt][h2 * 2 + 0] + bp.x;
                    o.y = acc[mt][nt][h2 * 2 + 1] + bp.y;
                    *(float2*)&C[(size_t)grow * PDIM + gcol] = o;
                }
            }
        }
    }
}

// -------- launch --------
extern "C" void kernel_launch(void* const* d_in, const int* in_sizes, int n_in,
                              void* d_out, int out_size) {
    const float* x       = (const float*)d_in[0];
    const int*   index_p = (const int*)  d_in[1];
    const float* W_proj  = (const float*)d_in[2];
    const float* b_proj  = (const float*)d_in[3];
    const float* W_out   = (const float*)d_in[4];
    const float* b_out   = (const float*)d_in[5];
    const float* w_mix   = (const float*)d_in[6];
    const float* b_mix   = (const float*)d_in[7];
    const float* decay   = (const float*)d_in[8];
    const float* caches  = (const float*)d_in[9];
    float* out = (float*)d_out;

    float *hidden, *xr, *wpt, *wot;
    cudaGetSymbolAddress((void**)&hidden, g_hidden);
    cudaGetSymbolAddress((void**)&xr,     g_X);
    cudaGetSymbolAddress((void**)&wpt,    g_Wpt);
    cudaGetSymbolAddress((void**)&wot,    g_Wot);

    const int SMEM_TOTAL = 4 * (128 * 128 + 256 * 128);   // 196608
    cudaFuncSetAttribute(gemm_mma<1>, cudaFuncAttributeMaxDynamicSharedMemorySize, SMEM_TOTAL);
    cudaFuncSetAttribute(gemm_mma<2>, cudaFuncAttributeMaxDynamicSharedMemorySize, SMEM_TOTAL);

    coef_kernel<<<1, 32>>>(w_mix, b_mix, decay, index_p);

    // x -> rna(tf32)
    {
        int n4 = (int)(((size_t)PB * PDIM) / 4);
        cvt_kernel<<<(n4 + 255) / 256, 256>>>(x, xr, n4);
    }
    // W_proj [16][4096][256] -> g_Wpt [16][256][4096] (rna)
    transpose_kernel<<<dim3(PHID / 32, PDIM / 32, PH), dim3(32, 8)>>>(W_proj, wpt, PDIM, PHID);
    // W_out [4096][4096] -> g_Wot [N][K] (rna)
    transpose_kernel<<<dim3(PDIM / 32, PDIM / 32, 1), dim3(32, 8)>>>(W_out, wot, PDIM, PDIM);

    dim3 grid(PDIM / 256, PB / 128);   // (16, 64)
    gemm_mma<1><<<grid, 256, SMEM_TOTAL>>>(xr, wpt, b_proj, caches, hidden);
    gemm_mma<2><<<grid, 256, SMEM_TOTAL>>>(hidden, wot, b_out, nullptr, out);
}

// round 7
// speedup vs baseline: 1.7468x; 1.7468x over previous
#include <cuda_runtime.h>
#include <cuda_fp16.h>
#include <cstdint>

#define PB   8192
#define PDIM 4096
#define PHID 256
#define PH   16
#define PSEQ 2048

// -------- device-global scratch (no allocs allowed) --------
__device__ __align__(128) __half g_hidden[(size_t)PB * PDIM];   // 64 MB (fp16 GEMM1 out)
__device__ __align__(128) __half g_Xh[(size_t)PB * PDIM];       // 64 MB (fp16 x)
__device__ __align__(128) __half g_Wpt[(size_t)PH * PHID * PDIM]; // 32 MB [n_global][k]
__device__ __align__(128) __half g_Wot[(size_t)PDIM * PDIM];    // 32 MB [n][k]
__device__ float g_coef[48];                                    // w[16], cc[16], b[16]

// -------- helpers --------
__device__ __forceinline__ uint32_t smem_u32(const void* p) {
    uint32_t a;
    asm("{ .reg .u64 t; cvta.to.shared.u64 t, %1; cvt.u32.u64 %0, t; }" : "=r"(a) : "l"(p));
    return a;
}
__device__ __forceinline__ void cp16(uint32_t dst, const void* src) {
    asm volatile("cp.async.cg.shared.global [%0], [%1], 16;" :: "r"(dst), "l"(src));
}
__device__ __forceinline__ void ldsm4(uint32_t* r, uint32_t addr) {
    asm volatile("ldmatrix.sync.aligned.m8n8.x4.shared.b16 {%0,%1,%2,%3}, [%4];"
                 : "=r"(r[0]), "=r"(r[1]), "=r"(r[2]), "=r"(r[3]) : "r"(addr));
}
// m16n8k16 fp16 inputs, f32 accumulate
__device__ __forceinline__ void mma_f16(float* d, const uint32_t* a, uint32_t b0, uint32_t b1) {
    asm volatile("mma.sync.aligned.m16n8k16.row.col.f32.f16.f16.f32 "
                 "{%0,%1,%2,%3}, {%4,%5,%6,%7}, {%8,%9}, {%0,%1,%2,%3};"
                 : "+f"(d[0]), "+f"(d[1]), "+f"(d[2]), "+f"(d[3])
                 : "r"(a[0]), "r"(a[1]), "r"(a[2]), "r"(a[3]), "r"(b0), "r"(b1));
}

// -------- small prep kernels --------
__global__ void coef_kernel(const float* __restrict__ w_mix,
                            const float* __restrict__ b_mix,
                            const float* __restrict__ decay_values,
                            const int* __restrict__ index_p) {
    int h = threadIdx.x;
    if (h < PH) {
        int idx = *index_p;
        float w = w_mix[h * PSEQ + idx];
        float b = b_mix[h * PSEQ + idx];
        float d = decay_values[h];
        d = fminf(fmaxf(d, 0.9f), 1.0f);
        d = powf(d, 0.25f);
        g_coef[h]      = w;
        g_coef[16 + h] = (h < PH / 2) ? (w * d) : d;
        g_coef[32 + h] = b;
    }
}

// f32 -> f16 convert, 8 elems/thread
__global__ void cvt_half_kernel(const float* __restrict__ in, __half* __restrict__ out, int n8) {
    int i = blockIdx.x * blockDim.x + threadIdx.x;
    if (i < n8) {
        float4 v0 = ((const float4*)in)[i * 2];
        float4 v1 = ((const float4*)in)[i * 2 + 1];
        __half2 h[4];
        h[0] = __floats2half2_rn(v0.x, v0.y);
        h[1] = __floats2half2_rn(v0.z, v0.w);
        h[2] = __floats2half2_rn(v1.x, v1.y);
        h[3] = __floats2half2_rn(v1.z, v1.w);
        ((uint4*)out)[i] = *(uint4*)h;
    }
}

// out[b][c][r] = f16(in[b][r][c])
__global__ void transpose_half_kernel(const float* __restrict__ in, __half* __restrict__ out,
                                      int rows, int cols) {
    __shared__ float t[32][33];
    const float* In = in + (size_t)blockIdx.z * rows * cols;
    __half* Out = out + (size_t)blockIdx.z * rows * cols;
    int r0 = blockIdx.y * 32, c0 = blockIdx.x * 32;
#pragma unroll
    for (int i = threadIdx.y; i < 32; i += 8)
        t[i][threadIdx.x] = In[(size_t)(r0 + i) * cols + c0 + threadIdx.x];
    __syncthreads();
#pragma unroll
    for (int i = threadIdx.y; i < 32; i += 8)
        Out[(size_t)(c0 + i) * rows + r0 + threadIdx.x] = __float2half_rn(t[threadIdx.x][i]);
}

// -------- FP16 mma.sync GEMM: C[8192,4096] = A[8192,4096] @ Bt[4096,4096]^T --------
// A, Bt fp16, k-contiguous. Tile 128x256x64, 8 warps (2Mx4N), 64x64 warp tiles,
// 4-stage cp.async (R4 ordering: issue at loop bottom), SW128 xor swizzle.
// MODE 1: head epilogue -> fp16 hidden; MODE 2: +bias -> f32 out.
template <int MODE>
__global__ void __launch_bounds__(256, 1)
gemm_mma(const __half* __restrict__ A, const __half* __restrict__ Bt,
         const float* __restrict__ bias, const float* __restrict__ caches,
         void* __restrict__ Cv) {
    constexpr int S = 4;
    constexpr int BK = 64;                     // f16 elems per stage
    constexpr int NCH = PDIM / BK;             // 64
    constexpr uint32_t A_BYTES = 128 * 128;    // 16 KB (128 rows x 128B)
    constexpr uint32_t STG = A_BYTES + 256 * 128;  // 48 KB

    extern __shared__ char smem[];
    const uint32_t sb = smem_u32(smem);
    const int tid = threadIdx.x;
    const int wid = tid >> 5, lane = tid & 31;
    const int wm = wid & 1;      // 2 warps along M
    const int wn = wid >> 1;     // 4 warps along N

    const int m0 = blockIdx.y * 128;
    const int n0 = blockIdx.x * 256;
    const __half* Ab = A + (size_t)m0 * PDIM;
    const __half* Bb = Bt + (size_t)n0 * PDIM;

    // cp.async coords: A 1024 chunks (4/thr), B 2048 chunks (8/thr); chunk=16B=8 f16
    int ar[4], ac[4]; uint32_t asw[4];
    int br[8], bc[8]; uint32_t bsw[8];
#pragma unroll
    for (int j = 0; j < 4; j++) {
        int id = tid + j * 256;
        ar[j] = id >> 3; ac[j] = id & 7;
        asw[j] = (uint32_t)ar[j] * 128 + ((((uint32_t)ac[j]) * 16) ^ ((((uint32_t)ar[j]) & 7) << 4));
    }
#pragma unroll
    for (int j = 0; j < 8; j++) {
        int id = tid + j * 256;
        br[j] = id >> 3; bc[j] = id & 7;
        bsw[j] = (uint32_t)br[j] * 128 + ((((uint32_t)bc[j]) * 16) ^ ((((uint32_t)br[j]) & 7) << 4));
    }

    float acc[4][8][4];
#pragma unroll
    for (int mt = 0; mt < 4; mt++)
#pragma unroll
        for (int nt = 0; nt < 8; nt++)
#pragma unroll
            for (int e = 0; e < 4; e++) acc[mt][nt][e] = 0.0f;

    // ldmatrix lane mapping (same for A and B): row = (lane&7)+((lane>>3)&1)*8,
    // +16B group = lane>>4.  mats: {r0-7 g0, r8-15 g0, r0-7 g1, r8-15 g1}
    const int lrow = (lane & 7) + (((lane >> 3) & 1) << 3);
    const int lgrp = lane >> 4;
    const int a_row = wm * 64 + lrow;   // + mt*16
    const int b_row = wn * 64 + lrow;   // + ntp*16

    auto issue = [&](int c) {
        const __half* ag = Ab + c * BK;
        const __half* bg = Bb + c * BK;
        uint32_t st = sb + (uint32_t)(c & (S - 1)) * STG;
#pragma unroll
        for (int j = 0; j < 4; j++)
            cp16(st + asw[j], ag + (size_t)ar[j] * PDIM + ac[j] * 8);
#pragma unroll
        for (int j = 0; j < 8; j++)
            cp16(st + A_BYTES + bsw[j], bg + (size_t)br[j] * PDIM + bc[j] * 8);
    };

    // prologue: 3 stages
#pragma unroll
    for (int c = 0; c < S - 1; c++) {
        issue(c);
        asm volatile("cp.async.commit_group;" ::: "memory");
    }

    for (int i = 0; i < NCH; i++) {
        asm volatile("cp.async.wait_group %0;" :: "n"(S - 2) : "memory");
        __syncthreads();

        uint32_t sa = sb + (uint32_t)(i & (S - 1)) * STG;
        uint32_t sB = sa + A_BYTES;

#pragma unroll
        for (int ks = 0; ks < 4; ks++) {          // 4 x k16
            const int gg = 2 * ks + lgrp;         // 16B group within 128B row
            uint32_t af[4][4], bf[4][4];
#pragma unroll
            for (int mt = 0; mt < 4; mt++) {
                int rr = a_row + mt * 16;
                ldsm4(af[mt], sa + (uint32_t)rr * 128 +
                              ((((uint32_t)gg) << 4) ^ ((((uint32_t)rr) & 7) << 4)));
            }
#pragma unroll
            for (int ntp = 0; ntp < 4; ntp++) {
                int rr = b_row + ntp * 16;
                ldsm4(bf[ntp], sB + (uint32_t)rr * 128 +
                               ((((uint32_t)gg) << 4) ^ ((((uint32_t)rr) & 7) << 4)));
            }
#pragma unroll
            for (int mt = 0; mt < 4; mt++)
#pragma unroll
                for (int nt = 0; nt < 8; nt++)
                    mma_f16(acc[mt][nt], af[mt],
                            bf[nt >> 1][nt & 1], bf[nt >> 1][(nt & 1) + 2]);
        }

        int c = i + S - 1;
        if (c < NCH) issue(c);
        asm volatile("cp.async.commit_group;" ::: "memory");
    }

    // -------- epilogue --------
    const int r = lane >> 2, qc = lane & 3;
    float wv = 0.f, ccf = 0.f, bvv = 0.f;
    if (MODE == 1) {
        wv  = g_coef[blockIdx.x];
        ccf = g_coef[16 + blockIdx.x];
        bvv = g_coef[32 + blockIdx.x];
    }
#pragma unroll
    for (int mt = 0; mt < 4; mt++) {
        const int grow0 = m0 + wm * 64 + mt * 16 + r;
#pragma unroll
        for (int nt = 0; nt < 8; nt++) {
            const int cloc = wn * 64 + nt * 8 + 2 * qc;   // col within 256-wide tile
            const int gcol = n0 + cloc;
            if (MODE == 1) {
                __half* C = (__half*)Cv;
                const float2 bp = *(const float2*)&bias[blockIdx.x * PHID + cloc];
#pragma unroll
                for (int h2 = 0; h2 < 2; h2++) {
                    const int grow = grow0 + h2 * 8;
                    const float2 cv = *(const float2*)
                        &caches[((size_t)blockIdx.x * PB + grow) * PHID + cloc];
                    __half2 o = __floats2half2_rn(
                        wv * (acc[mt][nt][h2 * 2 + 0] + bp.x) + ccf * cv.x + bvv,
                        wv * (acc[mt][nt][h2 * 2 + 1] + bp.y) + ccf * cv.y + bvv);
                    *(__half2*)&C[(size_t)grow * PDIM + gcol] = o;
                }
            } else {
                float* C = (float*)Cv;
                const float2 bp = *(const float2*)&bias[gcol];
#pragma unroll
                for (int h2 = 0; h2 < 2; h2++) {
                    const int grow = grow0 + h2 * 8;
                    float2 o;
                    o.x = acc[mt][nt][h2 * 2 + 0] + bp.x;
                    o.y = acc[mt][nt][h2 * 2 + 1] + bp.y;
                    *(float2*)&C[(size_t)grow * PDIM + gcol] = o;
                }
            }
        }
    }
}

// -------- launch --------
extern "C" void kernel_launch(void* const* d_in, const int* in_sizes, int n_in,
                              void* d_out, int out_size) {
    const float* x       = (const float*)d_in[0];
    const int*   index_p = (const int*)  d_in[1];
    const float* W_proj  = (const float*)d_in[2];
    const float* b_proj  = (const float*)d_in[3];
    const float* W_out   = (const float*)d_in[4];
    const float* b_out   = (const float*)d_in[5];
    const float* w_mix   = (const float*)d_in[6];
    const float* b_mix   = (const float*)d_in[7];
    const float* decay   = (const float*)d_in[8];
    const float* caches  = (const float*)d_in[9];
    float* out = (float*)d_out;

    __half *hidden, *xh, *wpt, *wot;
    cudaGetSymbolAddress((void**)&hidden, g_hidden);
    cudaGetSymbolAddress((void**)&xh,     g_Xh);
    cudaGetSymbolAddress((void**)&wpt,    g_Wpt);
    cudaGetSymbolAddress((void**)&wot,    g_Wot);

    const int SMEM_TOTAL = 4 * (128 * 128 + 256 * 128);   // 196608 (192 KB)
    cudaFuncSetAttribute(gemm_mma<1>, cudaFuncAttributeMaxDynamicSharedMemorySize, SMEM_TOTAL);
    cudaFuncSetAttribute(gemm_mma<2>, cudaFuncAttributeMaxDynamicSharedMemorySize, SMEM_TOTAL);

    coef_kernel<<<1, 32>>>(w_mix, b_mix, decay, index_p);

    // x -> fp16
    {
        int n8 = (int)(((size_t)PB * PDIM) / 8);
        cvt_half_kernel<<<(n8 + 255) / 256, 256>>>(x, xh, n8);
    }
    // W_proj [16][4096][256] -> g_Wpt fp16 [16][256][4096]
    transpose_half_kernel<<<dim3(PHID / 32, PDIM / 32, PH), dim3(32, 8)>>>(W_proj, wpt, PDIM, PHID);
    // W_out [4096][4096] -> g_Wot fp16 [N][K]
    transpose_half_kernel<<<dim3(PDIM / 32, PDIM / 32, 1), dim3(32, 8)>>>(W_out, wot, PDIM, PDIM);

    dim3 grid(PDIM / 256, PB / 128);   // (16, 64)
    gemm_mma<1><<<grid, 256, SMEM_TOTAL>>>(xh, wpt, b_proj, caches, hidden);
    gemm_mma<2><<<grid, 256, SMEM_TOTAL>>>(hidden, wot, b_out, nullptr, out);
}

// round 8
// speedup vs baseline: 1.7575x; 1.0061x over previous
#include <cuda_runtime.h>
#include <cuda_fp16.h>
#include <cstdint>

#define PB   8192
#define PDIM 4096
#define PHID 256
#define PH   16
#define PSEQ 2048

// -------- device-global scratch (no allocs allowed) --------
__device__ __align__(128) __half g_hidden[(size_t)PB * PDIM];   // 64 MB (fp16 GEMM1 out)
__device__ __align__(128) __half g_Xh[(size_t)PB * PDIM];       // 64 MB (fp16 x)
__device__ __align__(128) __half g_Wpt[(size_t)PH * PHID * PDIM]; // 32 MB [n_global][k]
__device__ __align__(128) __half g_Wot[(size_t)PDIM * PDIM];    // 32 MB [n][k]
__device__ float g_coef[48];                                    // w[16], cc[16], b[16]

// -------- helpers --------
__device__ __forceinline__ uint32_t smem_u32(const void* p) {
    uint32_t a;
    asm("{ .reg .u64 t; cvta.to.shared.u64 t, %1; cvt.u32.u64 %0, t; }" : "=r"(a) : "l"(p));
    return a;
}
__device__ __forceinline__ void cp16(uint32_t dst, const void* src) {
    asm volatile("cp.async.cg.shared.global [%0], [%1], 16;" :: "r"(dst), "l"(src));
}
__device__ __forceinline__ void ldsm4(uint32_t* r, uint32_t addr) {
    asm volatile("ldmatrix.sync.aligned.m8n8.x4.shared.b16 {%0,%1,%2,%3}, [%4];"
                 : "=r"(r[0]), "=r"(r[1]), "=r"(r[2]), "=r"(r[3]) : "r"(addr));
}
// m16n8k16 fp16 inputs, f32 accumulate
__device__ __forceinline__ void mma_f16(float* d, const uint32_t* a, uint32_t b0, uint32_t b1) {
    asm volatile("mma.sync.aligned.m16n8k16.row.col.f32.f16.f16.f32 "
                 "{%0,%1,%2,%3}, {%4,%5,%6,%7}, {%8,%9}, {%0,%1,%2,%3};"
                 : "+f"(d[0]), "+f"(d[1]), "+f"(d[2]), "+f"(d[3])
                 : "r"(a[0]), "r"(a[1]), "r"(a[2]), "r"(a[3]), "r"(b0), "r"(b1));
}

// -------- small prep kernels --------
__global__ void coef_kernel(const float* __restrict__ w_mix,
                            const float* __restrict__ b_mix,
                            const float* __restrict__ decay_values,
                            const int* __restrict__ index_p) {
    int h = threadIdx.x;
    if (h < PH) {
        int idx = *index_p;
        float w = w_mix[h * PSEQ + idx];
        float b = b_mix[h * PSEQ + idx];
        float d = decay_values[h];
        d = fminf(fmaxf(d, 0.9f), 1.0f);
        d = powf(d, 0.25f);
        g_coef[h]      = w;
        g_coef[16 + h] = (h < PH / 2) ? (w * d) : d;
        g_coef[32 + h] = b;
    }
}

// f32 -> f16 convert, 8 elems/thread
__global__ void cvt_half_kernel(const float* __restrict__ in, __half* __restrict__ out, int n8) {
    int i = blockIdx.x * blockDim.x + threadIdx.x;
    if (i < n8) {
        float4 v0 = ((const float4*)in)[i * 2];
        float4 v1 = ((const float4*)in)[i * 2 + 1];
        __half2 h[4];
        h[0] = __floats2half2_rn(v0.x, v0.y);
        h[1] = __floats2half2_rn(v0.z, v0.w);
        h[2] = __floats2half2_rn(v1.x, v1.y);
        h[3] = __floats2half2_rn(v1.z, v1.w);
        ((uint4*)out)[i] = *(uint4*)h;
    }
}

// out[b][c][r] = f16(in[b][r][c])
__global__ void transpose_half_kernel(const float* __restrict__ in, __half* __restrict__ out,
                                      int rows, int cols) {
    __shared__ float t[32][33];
    const float* In = in + (size_t)blockIdx.z * rows * cols;
    __half* Out = out + (size_t)blockIdx.z * rows * cols;
    int r0 = blockIdx.y * 32, c0 = blockIdx.x * 32;
#pragma unroll
    for (int i = threadIdx.y; i < 32; i += 8)
        t[i][threadIdx.x] = In[(size_t)(r0 + i) * cols + c0 + threadIdx.x];
    __syncthreads();
#pragma unroll
    for (int i = threadIdx.y; i < 32; i += 8)
        Out[(size_t)(c0 + i) * rows + r0 + threadIdx.x] = __float2half_rn(t[threadIdx.x][i]);
}

// -------- FP16 mma.sync GEMM: C[8192,4096] = A[8192,4096] @ Bt[4096,4096]^T --------
// Tile 128x128x64, 8 warps (2Mx4N -> 64x32 warp tiles), 3-stage cp.async,
// 96 KB smem/CTA -> 2 CTAs/SM (16 warps/SM for latency hiding).
// MODE 1: head epilogue -> fp16 hidden (head = blockIdx.x>>1); MODE 2: +bias -> f32 out.
template <int MODE>
__global__ void __launch_bounds__(256, 2)
gemm_mma(const __half* __restrict__ A, const __half* __restrict__ Bt,
         const float* __restrict__ bias, const float* __restrict__ caches,
         void* __restrict__ Cv) {
    constexpr int S = 3;
    constexpr int BK = 64;                     // f16 elems per stage
    constexpr int NCH = PDIM / BK;             // 64
    constexpr uint32_t A_BYTES = 128 * 128;    // 16 KB (128 rows x 128B)
    constexpr uint32_t STG = 2 * A_BYTES;      // 32 KB (A + B)

    extern __shared__ char smem[];
    const uint32_t sb = smem_u32(smem);
    const int tid = threadIdx.x;
    const int wid = tid >> 5, lane = tid & 31;
    const int wm = wid & 1;      // 2 warps along M (64 rows each)
    const int wn = wid >> 1;     // 4 warps along N (32 cols each)

    const int m0 = blockIdx.y * 128;
    const int n0 = blockIdx.x * 128;
    const __half* Ab = A + (size_t)m0 * PDIM;
    const __half* Bb = Bt + (size_t)n0 * PDIM;

    // cp.async coords: A and B each 128 rows x 128B -> 1024 chunks, 4/thread
    int cr[4], cc4[4]; uint32_t csw[4];
#pragma unroll
    for (int j = 0; j < 4; j++) {
        int id = tid + j * 256;
        cr[j] = id >> 3; cc4[j] = id & 7;
        csw[j] = (uint32_t)cr[j] * 128 + ((((uint32_t)cc4[j]) * 16) ^ ((((uint32_t)cr[j]) & 7) << 4));
    }

    float acc[4][4][4];
#pragma unroll
    for (int mt = 0; mt < 4; mt++)
#pragma unroll
        for (int nt = 0; nt < 4; nt++)
#pragma unroll
            for (int e = 0; e < 4; e++) acc[mt][nt][e] = 0.0f;

    // ldmatrix lane mapping: row = (lane&7)+((lane>>3)&1)*8, 16B group = lane>>4
    const int lrow = (lane & 7) + (((lane >> 3) & 1) << 3);
    const int lgrp = lane >> 4;
    const int a_row = wm * 64 + lrow;   // + mt*16
    const int b_row = wn * 32 + lrow;   // + ntp*16

    auto issue = [&](int c) {
        const __half* ag = Ab + c * BK;
        const __half* bg = Bb + c * BK;
        uint32_t st = sb + (uint32_t)(c % S) * STG;
#pragma unroll
        for (int j = 0; j < 4; j++)
            cp16(st + csw[j], ag + (size_t)cr[j] * PDIM + cc4[j] * 8);
#pragma unroll
        for (int j = 0; j < 4; j++)
            cp16(st + A_BYTES + csw[j], bg + (size_t)cr[j] * PDIM + cc4[j] * 8);
    };

    // prologue: 2 stages
#pragma unroll
    for (int c = 0; c < S - 1; c++) {
        issue(c);
        asm volatile("cp.async.commit_group;" ::: "memory");
    }

    for (int i = 0; i < NCH; i++) {
        asm volatile("cp.async.wait_group %0;" :: "n"(S - 2) : "memory");
        __syncthreads();

        uint32_t sa = sb + (uint32_t)(i % S) * STG;
        uint32_t sB = sa + A_BYTES;

#pragma unroll
        for (int ks = 0; ks < 4; ks++) {          // 4 x k16
            const int gg = 2 * ks + lgrp;
            uint32_t af[4][4], bf[2][4];
#pragma unroll
            for (int mt = 0; mt < 4; mt++) {
                int rr = a_row + mt * 16;
                ldsm4(af[mt], sa + (uint32_t)rr * 128 +
                              ((((uint32_t)gg) << 4) ^ ((((uint32_t)rr) & 7) << 4)));
            }
#pragma unroll
            for (int ntp = 0; ntp < 2; ntp++) {
                int rr = b_row + ntp * 16;
                ldsm4(bf[ntp], sB + (uint32_t)rr * 128 +
                               ((((uint32_t)gg) << 4) ^ ((((uint32_t)rr) & 7) << 4)));
            }
#pragma unroll
            for (int mt = 0; mt < 4; mt++)
#pragma unroll
                for (int nt = 0; nt < 4; nt++)
                    mma_f16(acc[mt][nt], af[mt],
                            bf[nt >> 1][nt & 1], bf[nt >> 1][(nt & 1) + 2]);
        }

        int c = i + S - 1;
        if (c < NCH) issue(c);
        asm volatile("cp.async.commit_group;" ::: "memory");
    }

    // -------- epilogue --------
    const int r = lane >> 2, qc = lane & 3;
    const int hhead = blockIdx.x >> 1;                // head (BN=128, 2 tiles per head)
    const int kkb = (blockIdx.x & 1) * 128;           // col base within head
    float wv = 0.f, ccf = 0.f, bvv = 0.f;
    if (MODE == 1) {
        wv  = g_coef[hhead];
        ccf = g_coef[16 + hhead];
        bvv = g_coef[32 + hhead];
    }
#pragma unroll
    for (int mt = 0; mt < 4; mt++) {
        const int grow0 = m0 + wm * 64 + mt * 16 + r;
#pragma unroll
        for (int nt = 0; nt < 4; nt++) {
            const int cloc = wn * 32 + nt * 8 + 2 * qc;   // col within 128-wide tile
            const int gcol = n0 + cloc;
            if (MODE == 1) {
                __half* C = (__half*)Cv;
                const float2 bp = *(const float2*)&bias[hhead * PHID + kkb + cloc];
#pragma unroll
                for (int h2 = 0; h2 < 2; h2++) {
                    const int grow = grow0 + h2 * 8;
                    const float2 cv = *(const float2*)
                        &caches[((size_t)hhead * PB + grow) * PHID + kkb + cloc];
                    __half2 o = __floats2half2_rn(
                        wv * (acc[mt][nt][h2 * 2 + 0] + bp.x) + ccf * cv.x + bvv,
                        wv * (acc[mt][nt][h2 * 2 + 1] + bp.y) + ccf * cv.y + bvv);
                    *(__half2*)&C[(size_t)grow * PDIM + gcol] = o;
                }
            } else {
                float* C = (float*)Cv;
                const float2 bp = *(const float2*)&bias[gcol];
#pragma unroll
                for (int h2 = 0; h2 < 2; h2++) {
                    const int grow = grow0 + h2 * 8;
                    float2 o;
                    o.x = acc[mt][nt][h2 * 2 + 0] + bp.x;
                    o.y = acc[mt][nt][h2 * 2 + 1] + bp.y;
                    *(float2*)&C[(size_t)grow * PDIM + gcol] = o;
                }
            }
        }
    }
}

// -------- launch --------
extern "C" void kernel_launch(void* const* d_in, const int* in_sizes, int n_in,
                              void* d_out, int out_size) {
    const float* x       = (const float*)d_in[0];
    const int*   index_p = (const int*)  d_in[1];
    const float* W_proj  = (const float*)d_in[2];
    const float* b_proj  = (const float*)d_in[3];
    const float* W_out   = (const float*)d_in[4];
    const float* b_out   = (const float*)d_in[5];
    const float* w_mix   = (const float*)d_in[6];
    const float* b_mix   = (const float*)d_in[7];
    const float* decay   = (const float*)d_in[8];
    const float* caches  = (const float*)d_in[9];
    float* out = (float*)d_out;

    __half *hidden, *xh, *wpt, *wot;
    cudaGetSymbolAddress((void**)&hidden, g_hidden);
    cudaGetSymbolAddress((void**)&xh,     g_Xh);
    cudaGetSymbolAddress((void**)&wpt,    g_Wpt);
    cudaGetSymbolAddress((void**)&wot,    g_Wot);

    const int SMEM_TOTAL = 3 * 2 * 128 * 128;   // 98304 (96 KB)
    cudaFuncSetAttribute(gemm_mma<1>, cudaFuncAttributeMaxDynamicSharedMemorySize, SMEM_TOTAL);
    cudaFuncSetAttribute(gemm_mma<2>, cudaFuncAttributeMaxDynamicSharedMemorySize, SMEM_TOTAL);

    coef_kernel<<<1, 32>>>(w_mix, b_mix, decay, index_p);

    // x -> fp16
    {
        int n8 = (int)(((size_t)PB * PDIM) / 8);
        cvt_half_kernel<<<(n8 + 255) / 256, 256>>>(x, xh, n8);
    }
    // W_proj [16][4096][256] -> g_Wpt fp16 [16][256][4096]
    transpose_half_kernel<<<dim3(PHID / 32, PDIM / 32, PH), dim3(32, 8)>>>(W_proj, wpt, PDIM, PHID);
    // W_out [4096][4096] -> g_Wot fp16 [N][K]
    transpose_half_kernel<<<dim3(PDIM / 32, PDIM / 32, 1), dim3(32, 8)>>>(W_out, wot, PDIM, PDIM);

    dim3 grid(PDIM / 128, PB / 128);   // (32, 64)
    gemm_mma<1><<<grid, 256, SMEM_TOTAL>>>(xh, wpt, b_proj, caches, hidden);
    gemm_mma<2><<<grid, 256, SMEM_TOTAL>>>(hidden, wot, b_out, nullptr, out);
}